// round 7
// baseline (speedup 1.0000x reference)
#include <cuda_runtime.h>
#include <math.h>

#define Bq 256
#define Nq 256
#define Dq 512
#define Cq 1024
#define NCHUNK 16
#define CH_ROWS (Nq / NCHUNK)   // 16 rows per fused block
#define KSPLIT 8
#define KCH (Dq / KSPLIT)       // 64

// Scratch (device globals — no allocation allowed)
__device__ float  g_txtn[Cq * Dq];                 // normalized text (2 MB)
__device__ float  g_ppart[Bq * NCHUNK * Dq];       // partial weighted sums (8 MB)
__device__ float2 g_meta[Bq * NCHUNK];             // (m, den) per partial
__device__ float  g_pooled[Bq * Dq];               // pooled normalized tokens
__device__ float  g_lpart[KSPLIT * Bq * Cq];       // partial logits (8 MB)

__device__ __forceinline__ void warp_sum2(float& a, float& b) {
#pragma unroll
    for (int o = 16; o; o >>= 1) {
        a += __shfl_xor_sync(0xffffffffu, a, o);
        b += __shfl_xor_sync(0xffffffffu, b, o);
    }
}

__device__ __forceinline__ void warp_sum4(float& a, float& b, float& c, float& d) {
#pragma unroll
    for (int o = 16; o; o >>= 1) {
        a += __shfl_xor_sync(0xffffffffu, a, o);
        b += __shfl_xor_sync(0xffffffffu, b, o);
        c += __shfl_xor_sync(0xffffffffu, c, o);
        d += __shfl_xor_sync(0xffffffffu, d, o);
    }
}

// packed fp32x2 helpers (Blackwell FFMA2)
__device__ __forceinline__ void fma2(unsigned long long& d,
                                     unsigned long long a,
                                     unsigned long long b) {
    asm("fma.rn.f32x2 %0, %1, %2, %0;" : "+l"(d) : "l"(a), "l"(b));
}
__device__ __forceinline__ unsigned long long dup2(float v) {
    unsigned long long r;
    asm("mov.b64 %0, {%1, %1};" : "=l"(r) : "f"(v));
    return r;
}
__device__ __forceinline__ unsigned long long pack2(float x, float y) {
    unsigned long long r;
    asm("mov.b64 %0, {%1, %2};" : "=l"(r) : "f"(x), "f"(y));
    return r;
}

// ---------------------------------------------------------------------------
// K1: L2-normalize text features; also zero the output scalar (for K5 atomic).
// One warp per row. grid = C/8, block = 256.
// ---------------------------------------------------------------------------
__global__ void k_txtnorm(const float* __restrict__ txt, float* __restrict__ out) {
    if (blockIdx.x == 0 && threadIdx.x == 0) out[0] = 0.f;
    int w = threadIdx.x >> 5, lane = threadIdx.x & 31;
    int row = blockIdx.x * 8 + w;
    const float4* src = (const float4*)(txt + (size_t)row * Dq);
    float4* dst = (float4*)(g_txtn + (size_t)row * Dq);
    float4 v[4];
    float ss = 0.f, dummy = 0.f;
#pragma unroll
    for (int i = 0; i < 4; i++) {
        v[i] = src[lane + 32 * i];
        ss += v[i].x * v[i].x + v[i].y * v[i].y + v[i].z * v[i].z + v[i].w * v[i].w;
    }
    warp_sum2(ss, dummy);
    float rn = 1.f / fmaxf(sqrtf(ss), 1e-12f);
#pragma unroll
    for (int i = 0; i < 4; i++) {
        float4 o;
        o.x = v[i].x * rn; o.y = v[i].y * rn; o.z = v[i].z * rn; o.w = v[i].w * rn;
        dst[lane + 32 * i] = o;
    }
}

// ---------------------------------------------------------------------------
// K2 (fused streaming pass): online softmax-weighted pooling, single read of
// toks (128 MB). grid = (NCHUNK, B) = 4096 blocks, block = 256 (8 warps x 2).
// ---------------------------------------------------------------------------
__global__ void k_fused(const float* __restrict__ toks,
                        const int* __restrict__ gt,
                        const float* __restrict__ p_log_attn_tau) {
    __shared__ float sm[8], sden[8];
    __shared__ float svec[8][Dq];

    int ch = blockIdx.x, b = blockIdx.y;
    int w = threadIdx.x >> 5, lane = threadIdx.x & 31;

    float at = expf(*p_log_attn_tau);
    at = fminf(fmaxf(at, 0.01f), 1.0f);
    float inv_at = 1.f / at;

    int g = __ldg(&gt[b]);
    const float4* xrow = (const float4*)(g_txtn + (size_t)g * Dq);
    float4 xv[4];
#pragma unroll
    for (int i = 0; i < 4; i++) xv[i] = xrow[lane + 32 * i];

    int row0 = b * Nq + ch * CH_ROWS + w * 2;     // this warp's 2 rows
    const float4* base = (const float4*)(toks + (size_t)row0 * Dq);

    float4 t0[4], t1[4];
#pragma unroll
    for (int i = 0; i < 4; i++)
        t0[i] = __ldcs(&base[lane + 32 * i]);
#pragma unroll
    for (int i = 0; i < 4; i++)
        t1[i] = __ldcs(&base[(size_t)(Dq / 4) + lane + 32 * i]);

    float ss0 = 0.f, dp0 = 0.f, ss1 = 0.f, dp1 = 0.f;
#pragma unroll
    for (int i = 0; i < 4; i++) {
        ss0 += t0[i].x * t0[i].x + t0[i].y * t0[i].y + t0[i].z * t0[i].z + t0[i].w * t0[i].w;
        dp0 += t0[i].x * xv[i].x + t0[i].y * xv[i].y + t0[i].z * xv[i].z + t0[i].w * xv[i].w;
        ss1 += t1[i].x * t1[i].x + t1[i].y * t1[i].y + t1[i].z * t1[i].z + t1[i].w * t1[i].w;
        dp1 += t1[i].x * xv[i].x + t1[i].y * xv[i].y + t1[i].z * xv[i].z + t1[i].w * xv[i].w;
    }
    warp_sum4(ss0, dp0, ss1, dp1);

    float rn0 = 1.f / fmaxf(sqrtf(ss0), 1e-12f);
    float rn1 = 1.f / fmaxf(sqrtf(ss1), 1e-12f);
    float s0 = dp0 * rn0 * inv_at;
    float s1 = dp1 * rn1 * inv_at;
    float m = fmaxf(s0, s1);
    float e0 = expf(s0 - m);
    float e1 = expf(s1 - m);
    float den = e0 + e1;
    float c0 = e0 * rn0, c1 = e1 * rn1;

    if (lane == 0) { sm[w] = m; sden[w] = den; }
    float4* sv = (float4*)svec[w];
#pragma unroll
    for (int i = 0; i < 4; i++) {
        float4 o;
        o.x = fmaf(c1, t1[i].x, c0 * t0[i].x);
        o.y = fmaf(c1, t1[i].y, c0 * t0[i].y);
        o.z = fmaf(c1, t1[i].z, c0 * t0[i].z);
        o.w = fmaf(c1, t1[i].w, c0 * t0[i].w);
        sv[lane + 32 * i] = o;
    }
    __syncthreads();

    float M = sm[0];
#pragma unroll
    for (int i = 1; i < 8; i++) M = fmaxf(M, sm[i]);
    float wsc[8];
    float denb = 0.f;
#pragma unroll
    for (int i = 0; i < 8; i++) { wsc[i] = expf(sm[i] - M); denb = fmaf(wsc[i], sden[i], denb); }

    int tid = threadIdx.x;
    float* outp = g_ppart + (size_t)(b * NCHUNK + ch) * Dq;
#pragma unroll
    for (int rep = 0; rep < 2; rep++) {
        int d = tid + rep * 256;
        float v = 0.f;
#pragma unroll
        for (int i = 0; i < 8; i++) v = fmaf(wsc[i], svec[i][d], v);
        outp[d] = v;
    }
    if (tid == 0) g_meta[b * NCHUNK + ch] = make_float2(M, denb);
}

// ---------------------------------------------------------------------------
// K3: combine NCHUNK partials per b -> pooled[b,:]. grid = B, block = 128.
// ---------------------------------------------------------------------------
__global__ void k_combine() {
    int b = blockIdx.x, tid = threadIdx.x;
    float2 mt[NCHUNK];
#pragma unroll
    for (int i = 0; i < NCHUNK; i++) mt[i] = g_meta[b * NCHUNK + i];
    float M = mt[0].x;
#pragma unroll
    for (int i = 1; i < NCHUNK; i++) M = fmaxf(M, mt[i].x);
    float den = 0.f;
    float sc[NCHUNK];
#pragma unroll
    for (int i = 0; i < NCHUNK; i++) { sc[i] = expf(mt[i].x - M); den = fmaf(sc[i], mt[i].y, den); }
    float inv_den = 1.f / den;

    const float4* part = (const float4*)(g_ppart + (size_t)b * NCHUNK * Dq);
    float4 acc = make_float4(0.f, 0.f, 0.f, 0.f);
#pragma unroll
    for (int i = 0; i < NCHUNK; i++) {
        float4 p = part[(size_t)i * (Dq / 4) + tid];
        acc.x = fmaf(sc[i], p.x, acc.x);
        acc.y = fmaf(sc[i], p.y, acc.y);
        acc.z = fmaf(sc[i], p.z, acc.z);
        acc.w = fmaf(sc[i], p.w, acc.w);
    }
    acc.x *= inv_den; acc.y *= inv_den; acc.z *= inv_den; acc.w *= inv_den;
    ((float4*)(g_pooled + (size_t)b * Dq))[tid] = acc;
}

// ---------------------------------------------------------------------------
// K4: partial logits = pooled[:, kchunk] @ txtn[:, kchunk]^T.
// 64b x 128c tile, BK=32, 256 thr, 4x8 micro via packed fp32x2 FMA.
// grid = (C/128, B/64, KSPLIT) = (8, 4, 8) = 256 blocks.
// Per kk per thread: 3 LDS.128 (48 B) for 32 FMA -> 1.5 B/FMA smem ratio.
// Column-paired accumulators: accp[i][j] = (acc[i][2j], acc[i][2j+1]);
// b-pairs come free from float4 halves, a is duplicated (4 movs).
// ---------------------------------------------------------------------------
__global__ void __launch_bounds__(256) k_gemm() {
    __shared__ __align__(16) float As[32][68];
    __shared__ __align__(16) float Bs[32][132];
    int tid = threadIdx.x;
    int c0 = blockIdx.x * 128;
    int b0 = blockIdx.y * 64;
    int ks = blockIdx.z;
    int kbase = ks * KCH;
    int tx = tid & 15, ty = tid >> 4;   // tx: col-group (8 cols), ty: row-group (4 rows)

    unsigned long long accp[4][4];
#pragma unroll
    for (int i = 0; i < 4; i++)
#pragma unroll
        for (int j = 0; j < 4; j++) accp[i][j] = 0ull;

    for (int k0 = kbase; k0 < kbase + KCH; k0 += 32) {
#pragma unroll
        for (int i = 0; i < 8; i++) {       // As: 64 rows x 32 k = 2048
            int idx = tid + i * 256;
            int r = idx >> 5, kk = idx & 31;
            As[kk][r] = g_pooled[(size_t)(b0 + r) * Dq + k0 + kk];
        }
#pragma unroll
        for (int i = 0; i < 16; i++) {      // Bs: 128 rows x 32 k = 4096
            int idx = tid + i * 256;
            int r = idx >> 5, kk = idx & 31;
            Bs[kk][r] = g_txtn[(size_t)(c0 + r) * Dq + k0 + kk];
        }
        __syncthreads();
#pragma unroll
        for (int kk = 0; kk < 32; kk++) {
            float4 a4 = *(const float4*)&As[kk][ty * 4];
            float4 bA = *(const float4*)&Bs[kk][tx * 8];
            float4 bB = *(const float4*)&Bs[kk][tx * 8 + 4];
            unsigned long long ad0 = dup2(a4.x);
            unsigned long long ad1 = dup2(a4.y);
            unsigned long long ad2 = dup2(a4.z);
            unsigned long long ad3 = dup2(a4.w);
            unsigned long long bp0 = pack2(bA.x, bA.y);
            unsigned long long bp1 = pack2(bA.z, bA.w);
            unsigned long long bp2 = pack2(bB.x, bB.y);
            unsigned long long bp3 = pack2(bB.z, bB.w);
            fma2(accp[0][0], ad0, bp0); fma2(accp[0][1], ad0, bp1);
            fma2(accp[0][2], ad0, bp2); fma2(accp[0][3], ad0, bp3);
            fma2(accp[1][0], ad1, bp0); fma2(accp[1][1], ad1, bp1);
            fma2(accp[1][2], ad1, bp2); fma2(accp[1][3], ad1, bp3);
            fma2(accp[2][0], ad2, bp0); fma2(accp[2][1], ad2, bp1);
            fma2(accp[2][2], ad2, bp2); fma2(accp[2][3], ad2, bp3);
            fma2(accp[3][0], ad3, bp0); fma2(accp[3][1], ad3, bp1);
            fma2(accp[3][2], ad3, bp2); fma2(accp[3][3], ad3, bp3);
        }
        __syncthreads();
    }

    float* dst = g_lpart + ((size_t)ks * Bq) * Cq;
#pragma unroll
    for (int i = 0; i < 4; i++) {
        float2 f0 = *(float2*)&accp[i][0];
        float2 f1 = *(float2*)&accp[i][1];
        float2 f2 = *(float2*)&accp[i][2];
        float2 f3 = *(float2*)&accp[i][3];
        float* row = &dst[(size_t)(b0 + ty * 4 + i) * Cq + c0 + tx * 8];
        *(float4*)row       = make_float4(f0.x, f0.y, f1.x, f1.y);
        *(float4*)(row + 4) = make_float4(f2.x, f2.y, f3.x, f3.y);
    }
}

// ---------------------------------------------------------------------------
// K5: cross entropy (summing KSPLIT logit partials) + mean via atomicAdd.
// grid = B, block = 256.
// ---------------------------------------------------------------------------
__global__ void k_ce(const float* __restrict__ p_log_tau,
                     const int* __restrict__ gt,
                     float* __restrict__ out) {
    __shared__ float red[256];
    int b = blockIdx.x, tid = threadIdx.x;
    float tau = expf(*p_log_tau);
    tau = fminf(fmaxf(tau, 0.01f), 1.0f);
    float inv = 1.f / tau;

    float l[4];
    float mx = -1e30f;
#pragma unroll
    for (int i = 0; i < 4; i++) {
        int idx = tid + i * 256;
        float v = 0.f;
#pragma unroll
        for (int ks = 0; ks < KSPLIT; ks++)
            v += g_lpart[((size_t)ks * Bq + b) * Cq + idx];
        l[i] = v * inv;
        mx = fmaxf(mx, l[i]);
    }
    red[tid] = mx;
    __syncthreads();
#pragma unroll
    for (int s = 128; s; s >>= 1) {
        if (tid < s) red[tid] = fmaxf(red[tid], red[tid + s]);
        __syncthreads();
    }
    mx = red[0];
    __syncthreads();

    float sum = 0.f;
#pragma unroll
    for (int i = 0; i < 4; i++) sum += expf(l[i] - mx);
    red[tid] = sum;
    __syncthreads();
#pragma unroll
    for (int s = 128; s; s >>= 1) {
        if (tid < s) red[tid] += red[tid + s];
        __syncthreads();
    }
    if (tid == 0) {
        int g = gt[b];
        float xg = 0.f;
#pragma unroll
        for (int ks = 0; ks < KSPLIT; ks++)
            xg += g_lpart[((size_t)ks * Bq + b) * Cq + g];
        xg *= inv;
        float nll = logf(red[0]) + mx - xg;
        atomicAdd(out, nll * (1.0f / (float)Bq));
    }
}

// ---------------------------------------------------------------------------
extern "C" void kernel_launch(void* const* d_in, const int* in_sizes, int n_in,
                              void* d_out, int out_size) {
    const float* toks         = (const float*)d_in[0];  // [B,N,D] f32
    const float* txt          = (const float*)d_in[1];  // [C,D]   f32
    const float* log_tau      = (const float*)d_in[2];  // scalar
    const float* log_attn_tau = (const float*)d_in[3];  // scalar
    const int*   gt           = (const int*)d_in[4];    // [B] int32
    float* out = (float*)d_out;

    k_txtnorm<<<Cq / 8, 256>>>(txt, out);
    dim3 gf(NCHUNK, Bq);
    k_fused<<<gf, 256>>>(toks, gt, log_attn_tau);
    k_combine<<<Bq, 128>>>();
    dim3 gg(Cq / 128, Bq / 64, KSPLIT);
    k_gemm<<<gg, 256>>>();
    k_ce<<<Bq, 256>>>(log_tau, gt, out);
}

// round 8
// speedup vs baseline: 1.2102x; 1.2102x over previous
#include <cuda_runtime.h>
#include <math.h>
#include <stdint.h>

#define Bq 256
#define Nq 256
#define Dq 512
#define Cq 1024
#define NCHUNK 8
#define CH_ROWS (Nq / NCHUNK)   // 32 rows per fused block
#define KSPLIT 8
#define KCH (Dq / KSPLIT)       // 64

// Scratch (device globals — no allocation allowed)
__device__ float  g_txtn[Cq * Dq];                 // normalized text (2 MB)
__device__ float  g_ppart[Bq * NCHUNK * Dq];       // partial weighted sums (4 MB)
__device__ float2 g_meta[Bq * NCHUNK];             // (m, den) per partial
__device__ float  g_pooled[Bq * Dq];               // pooled normalized tokens
__device__ float  g_lpart[KSPLIT * Bq * Cq];       // partial logits (8 MB)

__device__ __forceinline__ void warp_sum2(float& a, float& b) {
#pragma unroll
    for (int o = 16; o; o >>= 1) {
        a += __shfl_xor_sync(0xffffffffu, a, o);
        b += __shfl_xor_sync(0xffffffffu, b, o);
    }
}

__device__ __forceinline__ void warp_sum4(float& a, float& b, float& c, float& d) {
#pragma unroll
    for (int o = 16; o; o >>= 1) {
        a += __shfl_xor_sync(0xffffffffu, a, o);
        b += __shfl_xor_sync(0xffffffffu, b, o);
        c += __shfl_xor_sync(0xffffffffu, c, o);
        d += __shfl_xor_sync(0xffffffffu, d, o);
    }
}

__device__ __forceinline__ uint32_t f2tf32(float v) {
    uint32_t r;
    asm("cvt.rna.tf32.f32 %0, %1;" : "=r"(r) : "f"(v));
    return r;
}

// ---------------------------------------------------------------------------
// K1: L2-normalize text features; also zero the output scalar (for K5 atomic).
// One warp per row. grid = C/8, block = 256.
// ---------------------------------------------------------------------------
__global__ void k_txtnorm(const float* __restrict__ txt, float* __restrict__ out) {
    if (blockIdx.x == 0 && threadIdx.x == 0) out[0] = 0.f;
    int w = threadIdx.x >> 5, lane = threadIdx.x & 31;
    int row = blockIdx.x * 8 + w;
    const float4* src = (const float4*)(txt + (size_t)row * Dq);
    float4* dst = (float4*)(g_txtn + (size_t)row * Dq);
    float4 v[4];
    float ss = 0.f, dummy = 0.f;
#pragma unroll
    for (int i = 0; i < 4; i++) {
        v[i] = src[lane + 32 * i];
        ss += v[i].x * v[i].x + v[i].y * v[i].y + v[i].z * v[i].z + v[i].w * v[i].w;
    }
    warp_sum2(ss, dummy);
    float rn = 1.f / fmaxf(sqrtf(ss), 1e-12f);
#pragma unroll
    for (int i = 0; i < 4; i++) {
        float4 o;
        o.x = v[i].x * rn; o.y = v[i].y * rn; o.z = v[i].z * rn; o.w = v[i].w * rn;
        dst[lane + 32 * i] = o;
    }
}

// ---------------------------------------------------------------------------
// K2 (fused streaming pass): online softmax-weighted pooling, single read of
// toks (128 MB). Two rows per iteration for 2x MLP.
// grid = (NCHUNK, B) = 2048 blocks, block = 256 (8 warps x 4 rows).
// ---------------------------------------------------------------------------
__global__ void k_fused(const float* __restrict__ toks,
                        const int* __restrict__ gt,
                        const float* __restrict__ p_log_attn_tau) {
    __shared__ float sm[8], sden[8];
    __shared__ float svec[8][Dq];

    int ch = blockIdx.x, b = blockIdx.y;
    int w = threadIdx.x >> 5, lane = threadIdx.x & 31;

    float at = expf(*p_log_attn_tau);
    at = fminf(fmaxf(at, 0.01f), 1.0f);
    float inv_at = 1.f / at;

    int g = __ldg(&gt[b]);
    const float4* xrow = (const float4*)(g_txtn + (size_t)g * Dq);
    float4 xv[4];
#pragma unroll
    for (int i = 0; i < 4; i++) xv[i] = xrow[lane + 32 * i];

    int row0 = b * Nq + ch * CH_ROWS + w * 4;
    const float4* base = (const float4*)(toks + (size_t)row0 * Dq);

    float m = -1e30f, den = 0.f;
    float4 acc[4];
#pragma unroll
    for (int i = 0; i < 4; i++) acc[i] = make_float4(0.f, 0.f, 0.f, 0.f);

#pragma unroll
    for (int rp = 0; rp < 2; rp++) {
        float4 t0[4], t1[4];
#pragma unroll
        for (int i = 0; i < 4; i++)
            t0[i] = __ldcs(&base[(size_t)(2 * rp) * (Dq / 4) + lane + 32 * i]);
#pragma unroll
        for (int i = 0; i < 4; i++)
            t1[i] = __ldcs(&base[(size_t)(2 * rp + 1) * (Dq / 4) + lane + 32 * i]);

        float ss0 = 0.f, dp0 = 0.f, ss1 = 0.f, dp1 = 0.f;
#pragma unroll
        for (int i = 0; i < 4; i++) {
            ss0 += t0[i].x * t0[i].x + t0[i].y * t0[i].y + t0[i].z * t0[i].z + t0[i].w * t0[i].w;
            dp0 += t0[i].x * xv[i].x + t0[i].y * xv[i].y + t0[i].z * xv[i].z + t0[i].w * xv[i].w;
            ss1 += t1[i].x * t1[i].x + t1[i].y * t1[i].y + t1[i].z * t1[i].z + t1[i].w * t1[i].w;
            dp1 += t1[i].x * xv[i].x + t1[i].y * xv[i].y + t1[i].z * xv[i].z + t1[i].w * xv[i].w;
        }
        warp_sum4(ss0, dp0, ss1, dp1);

        float rn0 = 1.f / fmaxf(sqrtf(ss0), 1e-12f);
        float rn1 = 1.f / fmaxf(sqrtf(ss1), 1e-12f);
        float s0 = dp0 * rn0 * inv_at;
        float s1 = dp1 * rn1 * inv_at;
        float mnew = fmaxf(m, fmaxf(s0, s1));
        float scale = expf(m - mnew);
        float e0 = expf(s0 - mnew);
        float e1 = expf(s1 - mnew);
        den = den * scale + e0 + e1;
        float c0 = e0 * rn0, c1 = e1 * rn1;
#pragma unroll
        for (int i = 0; i < 4; i++) {
            acc[i].x = fmaf(c1, t1[i].x, fmaf(c0, t0[i].x, acc[i].x * scale));
            acc[i].y = fmaf(c1, t1[i].y, fmaf(c0, t0[i].y, acc[i].y * scale));
            acc[i].z = fmaf(c1, t1[i].z, fmaf(c0, t0[i].z, acc[i].z * scale));
            acc[i].w = fmaf(c1, t1[i].w, fmaf(c0, t0[i].w, acc[i].w * scale));
        }
        m = mnew;
    }

    if (lane == 0) { sm[w] = m; sden[w] = den; }
    float4* sv = (float4*)svec[w];
#pragma unroll
    for (int i = 0; i < 4; i++) sv[lane + 32 * i] = acc[i];
    __syncthreads();

    float M = sm[0];
#pragma unroll
    for (int i = 1; i < 8; i++) M = fmaxf(M, sm[i]);
    float wsc[8];
    float denb = 0.f;
#pragma unroll
    for (int i = 0; i < 8; i++) { wsc[i] = expf(sm[i] - M); denb = fmaf(wsc[i], sden[i], denb); }

    int tid = threadIdx.x;
    float* outp = g_ppart + (size_t)(b * NCHUNK + ch) * Dq;
#pragma unroll
    for (int rep = 0; rep < 2; rep++) {
        int d = tid + rep * 256;
        float v = 0.f;
#pragma unroll
        for (int i = 0; i < 8; i++) v = fmaf(wsc[i], svec[i][d], v);
        outp[d] = v;
    }
    if (tid == 0) g_meta[b * NCHUNK + ch] = make_float2(M, denb);
}

// ---------------------------------------------------------------------------
// K3: combine NCHUNK partials per b -> pooled[b,:]. grid = B, block = 128.
// ---------------------------------------------------------------------------
__global__ void k_combine() {
    int b = blockIdx.x, tid = threadIdx.x;
    float2 mt[NCHUNK];
#pragma unroll
    for (int i = 0; i < NCHUNK; i++) mt[i] = g_meta[b * NCHUNK + i];
    float M = mt[0].x;
#pragma unroll
    for (int i = 1; i < NCHUNK; i++) M = fmaxf(M, mt[i].x);
    float den = 0.f;
    float sc[NCHUNK];
#pragma unroll
    for (int i = 0; i < NCHUNK; i++) { sc[i] = expf(mt[i].x - M); den = fmaf(sc[i], mt[i].y, den); }
    float inv_den = 1.f / den;

    const float4* part = (const float4*)(g_ppart + (size_t)b * NCHUNK * Dq);
    float4 acc = make_float4(0.f, 0.f, 0.f, 0.f);
#pragma unroll
    for (int i = 0; i < NCHUNK; i++) {
        float4 p = part[(size_t)i * (Dq / 4) + tid];
        acc.x = fmaf(sc[i], p.x, acc.x);
        acc.y = fmaf(sc[i], p.y, acc.y);
        acc.z = fmaf(sc[i], p.z, acc.z);
        acc.w = fmaf(sc[i], p.w, acc.w);
    }
    acc.x *= inv_den; acc.y *= inv_den; acc.z *= inv_den; acc.w *= inv_den;
    ((float4*)(g_pooled + (size_t)b * Dq))[tid] = acc;
}

// ---------------------------------------------------------------------------
// K4: partial logits via TF32 mma.sync (m16n8k8, fp32 accumulate).
// CTA = 256 thr = 8 warps (2 M-warps x 4 N-warps), tile 64 x 128, KCH = 64.
// grid = (C/128, B/64, KSPLIT) = (8, 4, 8) = 256 CTAs.
// smem padded to 68 floats/row -> fragment LDS bank = lane (conflict-free).
// ---------------------------------------------------------------------------
__global__ void __launch_bounds__(256) k_gemm() {
    __shared__ __align__(16) uint32_t As[64][68];    // [m][k] tf32
    __shared__ __align__(16) uint32_t Bs[128][68];   // [n][k] tf32

    int tid = threadIdx.x;
    int c0 = blockIdx.x * 128;
    int b0 = blockIdx.y * 64;
    int kbase = blockIdx.z * KCH;

    int warp = tid >> 5, lane = tid & 31;
    int warpM = warp & 1;          // 0..1  -> 32 rows each
    int warpN = warp >> 1;         // 0..3  -> 32 cols each
    int qg = lane >> 2;            // quad group 0..7
    int qt = lane & 3;             // thread in quad 0..3

    // ---- load + tf32-convert tiles ----
    {
        int r = tid >> 4;          // 0..15
        int cc = (tid & 15) * 4;   // 0..60
#pragma unroll
        for (int i = 0; i < 4; i++) {   // As: 64 rows
            int row = r + 16 * i;
            float4 v = *(const float4*)&g_pooled[(size_t)(b0 + row) * Dq + kbase + cc];
            uint4 u = make_uint4(f2tf32(v.x), f2tf32(v.y), f2tf32(v.z), f2tf32(v.w));
            *(uint4*)&As[row][cc] = u;
        }
#pragma unroll
        for (int i = 0; i < 8; i++) {   // Bs: 128 rows
            int row = r + 16 * i;
            float4 v = *(const float4*)&g_txtn[(size_t)(c0 + row) * Dq + kbase + cc];
            uint4 u = make_uint4(f2tf32(v.x), f2tf32(v.y), f2tf32(v.z), f2tf32(v.w));
            *(uint4*)&Bs[row][cc] = u;
        }
    }
    __syncthreads();

    float d[2][4][4];   // [mtile][ntile][frag]
#pragma unroll
    for (int mt = 0; mt < 2; mt++)
#pragma unroll
        for (int nt = 0; nt < 4; nt++)
#pragma unroll
            for (int f = 0; f < 4; f++) d[mt][nt][f] = 0.f;

#pragma unroll
    for (int ks = 0; ks < KCH / 8; ks++) {
        int k = ks * 8;
        uint32_t a[2][4];
#pragma unroll
        for (int mt = 0; mt < 2; mt++) {
            int row = warpM * 32 + mt * 16 + qg;
            a[mt][0] = As[row][k + qt];
            a[mt][1] = As[row + 8][k + qt];
            a[mt][2] = As[row][k + qt + 4];
            a[mt][3] = As[row + 8][k + qt + 4];
        }
        uint32_t bf[4][2];
#pragma unroll
        for (int nt = 0; nt < 4; nt++) {
            int n = warpN * 32 + nt * 8 + qg;
            bf[nt][0] = Bs[n][k + qt];
            bf[nt][1] = Bs[n][k + qt + 4];
        }
#pragma unroll
        for (int mt = 0; mt < 2; mt++)
#pragma unroll
            for (int nt = 0; nt < 4; nt++) {
                asm volatile(
                    "mma.sync.aligned.m16n8k8.row.col.f32.tf32.tf32.f32 "
                    "{%0,%1,%2,%3}, {%4,%5,%6,%7}, {%8,%9}, {%0,%1,%2,%3};"
                    : "+f"(d[mt][nt][0]), "+f"(d[mt][nt][1]),
                      "+f"(d[mt][nt][2]), "+f"(d[mt][nt][3])
                    : "r"(a[mt][0]), "r"(a[mt][1]), "r"(a[mt][2]), "r"(a[mt][3]),
                      "r"(bf[nt][0]), "r"(bf[nt][1]));
            }
    }

    // ---- epilogue: float2 stores ----
    float* dst = g_lpart + ((size_t)blockIdx.z * Bq) * Cq;
#pragma unroll
    for (int mt = 0; mt < 2; mt++) {
        int row0 = b0 + warpM * 32 + mt * 16 + qg;
#pragma unroll
        for (int nt = 0; nt < 4; nt++) {
            int col = c0 + warpN * 32 + nt * 8 + 2 * qt;
            *(float2*)&dst[(size_t)row0 * Cq + col] =
                make_float2(d[mt][nt][0], d[mt][nt][1]);
            *(float2*)&dst[(size_t)(row0 + 8) * Cq + col] =
                make_float2(d[mt][nt][2], d[mt][nt][3]);
        }
    }
}

// ---------------------------------------------------------------------------
// K5: cross entropy (summing KSPLIT logit partials) + mean via atomicAdd.
// grid = B, block = 256.
// ---------------------------------------------------------------------------
__global__ void k_ce(const float* __restrict__ p_log_tau,
                     const int* __restrict__ gt,
                     float* __restrict__ out) {
    __shared__ float red[256];
    int b = blockIdx.x, tid = threadIdx.x;
    float tau = expf(*p_log_tau);
    tau = fminf(fmaxf(tau, 0.01f), 1.0f);
    float inv = 1.f / tau;

    float l[4];
    float mx = -1e30f;
#pragma unroll
    for (int i = 0; i < 4; i++) {
        int idx = tid + i * 256;
        float v = 0.f;
#pragma unroll
        for (int ks = 0; ks < KSPLIT; ks++)
            v += g_lpart[((size_t)ks * Bq + b) * Cq + idx];
        l[i] = v * inv;
        mx = fmaxf(mx, l[i]);
    }
    red[tid] = mx;
    __syncthreads();
#pragma unroll
    for (int s = 128; s; s >>= 1) {
        if (tid < s) red[tid] = fmaxf(red[tid], red[tid + s]);
        __syncthreads();
    }
    mx = red[0];
    __syncthreads();

    float sum = 0.f;
#pragma unroll
    for (int i = 0; i < 4; i++) sum += expf(l[i] - mx);
    red[tid] = sum;
    __syncthreads();
#pragma unroll
    for (int s = 128; s; s >>= 1) {
        if (tid < s) red[tid] += red[tid + s];
        __syncthreads();
    }
    if (tid == 0) {
        int g = gt[b];
        float xg = 0.f;
#pragma unroll
        for (int ks = 0; ks < KSPLIT; ks++)
            xg += g_lpart[((size_t)ks * Bq + b) * Cq + g];
        xg *= inv;
        float nll = logf(red[0]) + mx - xg;
        atomicAdd(out, nll * (1.0f / (float)Bq));
    }
}

// ---------------------------------------------------------------------------
extern "C" void kernel_launch(void* const* d_in, const int* in_sizes, int n_in,
                              void* d_out, int out_size) {
    const float* toks         = (const float*)d_in[0];  // [B,N,D] f32
    const float* txt          = (const float*)d_in[1];  // [C,D]   f32
    const float* log_tau      = (const float*)d_in[2];  // scalar
    const float* log_attn_tau = (const float*)d_in[3];  // scalar
    const int*   gt           = (const int*)d_in[4];    // [B] int32
    float* out = (float*)d_out;

    k_txtnorm<<<Cq / 8, 256>>>(txt, out);
    dim3 gf(NCHUNK, Bq);
    k_fused<<<gf, 256>>>(toks, gt, log_attn_tau);
    k_combine<<<Bq, 128>>>();
    dim3 gg(Cq / 128, Bq / 64, KSPLIT);
    k_gemm<<<gg, 256>>>();
    k_ce<<<Bq, 256>>>(log_tau, gt, out);
}